// round 17
// baseline (speedup 1.0000x reference)
#include <cuda_runtime.h>
#include <cuda_bf16.h>
#include <cuda_fp16.h>
#include <math.h>
#include <stdint.h>

#define B_   2
#define N_   2048
#define D_   1024
#define INT_ 256
#define H_   4
#define HD_  64
#define HID_ 512
#define L_   6
#define M_   (B_*N_)   // 4096 rows

typedef __nv_bfloat16 bf16;

// ==================== scratch ====================
__device__ float g_X  [M_ * D_];
__device__ float g_H  [M_ * INT_];
__device__ bf16  g_qkbf[M_ * 512];           // [row][ Qh0..Qh3 | Kh0..Kh3 ] (rope+scale applied)
__device__ __half g_vh [M_ * 256];           // [row][ Vh0..Vh3 ] fp16
__device__ bf16  g_xbf [M_ * D_];
__device__ bf16  g_hnbf[M_ * INT_];
__device__ bf16  g_attbf[M_ * INT_];
__device__ bf16  g_g1bf[M_ * HID_];
__device__ bf16  g_hbf [M_ * INT_];
__device__ __half g_Opart[4 * 8 * N_ * 64]; // [chunk][bh][row][64] fp16
__device__ float g_ml   [4 * 8 * N_ * 2];    // [chunk][bh][row][{m,l}]  (m in log2 domain)
__device__ float2 g_cs  [N_ * 32];           // rope {cos,sin} per (n,d)
__device__ float  g_lns [N_];                // per-n q scale: max(1,log2(n+1)/6)*0.125*log2e
// bf16 weights
__device__ bf16 g_wdown[L_ * INT_ * D_];
__device__ bf16 g_wqkv [L_ * 3 * INT_ * INT_];
__device__ bf16 g_wproj[L_ * INT_ * INT_];
__device__ bf16 g_wm1  [L_ * HID_ * INT_];
__device__ bf16 g_wm2  [L_ * INT_ * HID_];
__device__ bf16 g_wup  [L_ * D_ * INT_];

// ==================== helpers ====================
__device__ __forceinline__ uint32_t packbf(float a, float b) {
    __nv_bfloat162 t = __floats2bfloat162_rn(a, b);
    return *reinterpret_cast<uint32_t*>(&t);
}
__device__ __forceinline__ uint32_t packh(float a, float b) {
    __half2 t = __floats2half2_rn(a, b);
    return *reinterpret_cast<uint32_t*>(&t);
}
__device__ __forceinline__ void mma16816(float* d, const uint32_t* a, uint32_t b0, uint32_t b1) {
    asm volatile(
        "mma.sync.aligned.m16n8k16.row.col.f32.bf16.bf16.f32 "
        "{%0,%1,%2,%3}, {%4,%5,%6,%7}, {%8,%9}, {%0,%1,%2,%3};"
        : "+f"(d[0]), "+f"(d[1]), "+f"(d[2]), "+f"(d[3])
        : "r"(a[0]), "r"(a[1]), "r"(a[2]), "r"(a[3]), "r"(b0), "r"(b1));
}
__device__ __forceinline__ void mma16816h(float* d, const uint32_t* a, uint32_t b0, uint32_t b1) {
    asm volatile(
        "mma.sync.aligned.m16n8k16.row.col.f32.f16.f16.f32 "
        "{%0,%1,%2,%3}, {%4,%5,%6,%7}, {%8,%9}, {%0,%1,%2,%3};"
        : "+f"(d[0]), "+f"(d[1]), "+f"(d[2]), "+f"(d[3])
        : "r"(a[0]), "r"(a[1]), "r"(a[2]), "r"(a[3]), "r"(b0), "r"(b1));
}
#define LDSM4(r0, r1, r2, r3, addr) \
    asm volatile("ldmatrix.sync.aligned.m8n8.x4.shared.b16 {%0,%1,%2,%3}, [%4];" \
        : "=r"(r0), "=r"(r1), "=r"(r2), "=r"(r3) : "r"(addr))
// two exp2's in one MUFU op; input floats, output packed f16x2
__device__ __forceinline__ uint32_t ex2_h2(float a, float b) {
    __half2 h = __floats2half2_rn(a, b);
    uint32_t u = *reinterpret_cast<uint32_t*>(&h);
    asm("ex2.approx.f16x2 %0, %0;" : "+r"(u));
    return u;
}
__device__ __forceinline__ uint32_t smem_u32(const void* p) {
    uint32_t a;
    asm("{ .reg .u64 t; cvta.to.shared.u64 t, %1; cvt.u32.u64 %0, t; }" : "=r"(a) : "l"(p));
    return a;
}
__device__ __forceinline__ void cp16(uint32_t dst, const void* src) {
    asm volatile("cp.async.cg.shared.global [%0], [%1], 16;" :: "r"(dst), "l"(src));
}
#define CP_COMMIT() asm volatile("cp.async.commit_group;")
#define CP_WAIT(n)  asm volatile("cp.async.wait_group %0;" :: "n"(n))

// ==================== rope table init ====================
__global__ __launch_bounds__(256) void rope_init() {
    int i = blockIdx.x * 256 + threadIdx.x;   // < N_*32
    int n = i >> 5, d = i & 31;
    float ph = (float)n * exp2f((float)d * (-13.287712379549449f / 32.f));
    float sn, cs;
    sincosf(ph, &sn, &cs);
    g_cs[i] = make_float2(cs, sn);
    if (d == 0) {
        const float LOG2E = 1.4426950408889634f;
        g_lns[n] = fmaxf(1.f, log2f((float)(n + 1)) * (1.f / 6.f)) * (0.125f * LOG2E);
    }
}

// ==================== batched fp32 -> bf16 convert (one launch) ====================
struct ConvArgs {
    const float* src[7];
    bf16* dst[7];
    unsigned end[7];    // prefix ends, float4 units
};
__global__ __launch_bounds__(256) void conv_all(ConvArgs a, unsigned total) {
    unsigned f4 = blockIdx.x * 256 + threadIdx.x;
    if (f4 >= total) return;
    int s = 0;
#pragma unroll
    for (int i = 0; i < 6; i++) if (f4 >= a.end[s]) s++;
    unsigned lo = f4 - (s ? a.end[s - 1] : 0);
    float4 v = ((const float4*)a.src[s])[lo];
    uint2 u = make_uint2(packbf(v.x, v.y), packbf(v.z, v.w));
    ((uint2*)a.dst[s])[lo] = u;
}

// ==================== 3-stage cp.async mma GEMM (ldmatrix fragments) ====
// C[M,N] = A[M,K] @ W[N,K]^T. Tile 64x64, 4 warps (warp 32x32), K chunk 64.
// EPI: 0 = +bias -> fp32 C ; 1 = gelu(+bias) -> bf16 Cbf only ;
//      2 = res + (+bias) -> fp32 C (+ optional bf16 Cbf) ;
//      3 = res + gamma*(+bias) -> fp32 C (+ optional bf16 Cbf) ;
//      5 = fused qkv rope epilogue (BN=64 tiles); res = rope cs table, gamma = logn table
__device__ __forceinline__ float gelu_f(float x) {
    return 0.5f * x * (1.0f + erff(x * 0.70710678118654752440f));
}

#define BM_ 64
#define BN_ 64
#define WM_G 32
#define GTHREADS 128

template<int EPI>
__global__ __launch_bounds__(GTHREADS, 4) void gemm_cp(
    const bf16* __restrict__ A, const bf16* __restrict__ W,
    const float* __restrict__ bias, const float* __restrict__ res,
    const float* __restrict__ gamma, float* __restrict__ C,
    bf16* __restrict__ Cbf, __half* __restrict__ Vh, int K, int N)
{
    constexpr int MA = WM_G / 16;                  // 2
    constexpr int ALOOP = BM_ * 8 / GTHREADS;      // 4
    constexpr int BLOOP = BN_ * 8 / GTHREADS;      // 4
    constexpr uint32_t ABYTES = BM_ * 72 * 2;
    constexpr uint32_t BBYTES = BN_ * 72 * 2;

    extern __shared__ bf16 sm[];
    bf16* As = sm;                    // [3][BM][72]
    bf16* Bs = sm + 3 * BM_ * 72;     // [3][BN][72]
    const uint32_t sA = smem_u32(As);
    const uint32_t sB = smem_u32(Bs);

    const int tid  = threadIdx.x;
    const int lane = tid & 31;
    const int wid  = tid >> 5;
    const int g  = lane >> 2;
    const int tg = lane & 3;
    const int wm = wid & 1;          // 2 warps in M
    const int wn = wid >> 1;         // 2 warps in N
    const int bm = blockIdx.y * BM_;
    const int bn = blockIdx.x * BN_;

    // ldmatrix lane-part offsets (bytes)
    const uint32_t a_lo = (uint32_t)(((lane & 15) * 72 + ((lane >> 4) << 3)) * 2);
    const int q8 = lane >> 3;
    const uint32_t b_lo = (uint32_t)(((((q8 >> 1) << 3) + (lane & 7)) * 72 + ((q8 & 1) << 3)) * 2);

    float acc[MA][4][4];
#pragma unroll
    for (int ma = 0; ma < MA; ma++)
#pragma unroll
        for (int na = 0; na < 4; na++)
#pragma unroll
            for (int r = 0; r < 4; r++) acc[ma][na][r] = 0.f;

    const bf16* Ab = A + (size_t)bm * K;
    const bf16* Wb = W + (size_t)bn * K;
    const int CH = K >> 6;

    auto issue = [&](int c) {
        const int st = c % 3;
        const int kof = c * 64;
#pragma unroll
        for (int i = 0; i < ALOOP; i++) {
            int v = tid + i * GTHREADS;
            int r = v >> 3, s = v & 7;
            cp16(sA + (uint32_t)((st * BM_ + r) * 72 + s * 8) * 2,
                 Ab + (size_t)r * K + kof + s * 8);
        }
#pragma unroll
        for (int i = 0; i < BLOOP; i++) {
            int v = tid + i * GTHREADS;
            int r = v >> 3, s = v & 7;
            cp16(sB + (uint32_t)((st * BN_ + r) * 72 + s * 8) * 2,
                 Wb + (size_t)r * K + kof + s * 8);
        }
        CP_COMMIT();
    };

    issue(0);
    issue(1);
    for (int c = 0; c < CH; c++) {
        if (c + 1 < CH) { CP_WAIT(1); }
        else            { CP_WAIT(0); }
        __syncthreads();
        if (c + 2 < CH) issue(c + 2);

        const int st = c % 3;
        const uint32_t aBase = sA + (uint32_t)st * ABYTES + (uint32_t)(wm * WM_G) * 144 + a_lo;
        const uint32_t bBase = sB + (uint32_t)st * BBYTES + (uint32_t)(wn * 32) * 144 + b_lo;
#pragma unroll
        for (int kc = 0; kc < 4; kc++) {
            uint32_t b01[4], b23[4];
            LDSM4(b01[0], b01[1], b01[2], b01[3], bBase + kc * 32);
            LDSM4(b23[0], b23[1], b23[2], b23[3], bBase + 16 * 144 + kc * 32);
#pragma unroll
            for (int ma = 0; ma < MA; ma++) {
                uint32_t af[4];
                LDSM4(af[0], af[1], af[2], af[3], aBase + (uint32_t)(ma * 16) * 144 + kc * 32);
                mma16816(acc[ma][0], af, b01[0], b01[1]);
                mma16816(acc[ma][1], af, b01[2], b01[3]);
                mma16816(acc[ma][2], af, b23[0], b23[1]);
                mma16816(acc[ma][3], af, b23[2], b23[3]);
            }
        }
    }
    __syncthreads();   // protect smem reuse in EPI5; orders last reads

    // ---------------- epilogue ----------------
    if (EPI == 5) {
        // qkv GEMM, BN=64 tiles: bn in {0..192}=Q, {256..448}=K, {512..704}=V.
        if (bn >= 512) {
#pragma unroll
            for (int ma = 0; ma < MA; ma++) {
                const int row0 = bm + wm * WM_G + ma * 16 + g;
#pragma unroll
                for (int na = 0; na < 4; na++) {
                    const int vcol = (bn - 512) + wn * 32 + na * 8 + tg * 2;
                    *(uint32_t*)(Vh + (size_t)row0 * 256 + vcol) = packh(acc[ma][na][0], acc[ma][na][1]);
                    *(uint32_t*)(Vh + (size_t)(row0 + 8) * 256 + vcol) = packh(acc[ma][na][2], acc[ma][na][3]);
                }
            }
        } else {
            // stage fp32 tile in smem, then rope pass using precomputed tables
            float* fbuf = (float*)sm;   // [BM][68]
#pragma unroll
            for (int ma = 0; ma < MA; ma++) {
                const int r0 = wm * WM_G + ma * 16 + g;
#pragma unroll
                for (int na = 0; na < 4; na++) {
                    const int col = wn * 32 + na * 8 + tg * 2;
                    *(float2*)&fbuf[r0 * 68 + col]       = make_float2(acc[ma][na][0], acc[ma][na][1]);
                    *(float2*)&fbuf[(r0 + 8) * 68 + col] = make_float2(acc[ma][na][2], acc[ma][na][3]);
                }
            }
            __syncthreads();
            const float2* cst = (const float2*)res;
            const bool isQ = (bn < 256);
            constexpr int ITERS = BM_ * 32 / GTHREADS;   // 16
#pragma unroll 4
            for (int i = 0; i < ITERS; i++) {
                int pi = tid + i * GTHREADS;    // 0 .. BM*32-1
                int row = pi >> 5;
                int d  = pi & 31;
                float f0 = fbuf[row * 68 + d];
                float f1 = fbuf[row * 68 + d + 32];
                int n = (bm + row) & (N_ - 1);
                float2 t = cst[n * 32 + d];
                float sc = isQ ? gamma[n] : 1.f;
                size_t R = (size_t)(bm + row);
                Cbf[R * 512 + bn + d]      = __float2bfloat16((f0 * t.x - f1 * t.y) * sc);
                Cbf[R * 512 + bn + d + 32] = __float2bfloat16((f1 * t.x + f0 * t.y) * sc);
            }
        }
        return;
    }

#pragma unroll
    for (int ma = 0; ma < MA; ma++) {
        const int row0 = bm + wm * WM_G + ma * 16 + g;
        const int row1 = row0 + 8;
#pragma unroll
        for (int na = 0; na < 4; na++) {
            const int col = bn + wn * 32 + na * 8 + tg * 2;
            float bx = 0.f, by = 0.f;
            if (bias) {
                float2 b2 = *(const float2*)(bias + col);
                bx = b2.x; by = b2.y;
            }
            float v00 = acc[ma][na][0] + bx, v01 = acc[ma][na][1] + by;
            float v10 = acc[ma][na][2] + bx, v11 = acc[ma][na][3] + by;
            const size_t o0 = (size_t)row0 * N + col;
            const size_t o1 = (size_t)row1 * N + col;
            if (EPI == 1) {
                v00 = gelu_f(v00); v01 = gelu_f(v01);
                v10 = gelu_f(v10); v11 = gelu_f(v11);
            } else if (EPI == 2) {
                float2 r0 = *(const float2*)(res + o0);
                float2 r1 = *(const float2*)(res + o1);
                v00 += r0.x; v01 += r0.y; v10 += r1.x; v11 += r1.y;
            } else if (EPI == 3) {
                float2 r0 = *(const float2*)(res + o0);
                float2 r1 = *(const float2*)(res + o1);
                float2 g2 = *(const float2*)(gamma + col);
                v00 = r0.x + g2.x * v00; v01 = r0.y + g2.y * v01;
                v10 = r1.x + g2.x * v10; v11 = r1.y + g2.y * v11;
            }
            if (EPI != 1) {
                *(float2*)(C + o0) = make_float2(v00, v01);
                *(float2*)(C + o1) = make_float2(v10, v11);
            }
            if (EPI == 1 || Cbf != nullptr) {
                *(uint32_t*)(Cbf + o0) = packbf(v00, v01);
                *(uint32_t*)(Cbf + o1) = packbf(v10, v11);
            }
        }
    }
}

// ==================== LayerNorm, 2 rows per warp, float4 path ==========
__global__ __launch_bounds__(256) void ln_kernel(
    const float* __restrict__ in, const float* __restrict__ s,
    const float* __restrict__ b, bf16* __restrict__ out)
{
    int gw   = (blockIdx.x * blockDim.x + threadIdx.x) >> 5;   // warp id, < M_/2
    int lane = threadIdx.x & 31;
    int rowA = gw * 2, rowB = rowA + 1;
    if (rowB >= M_) return;
    const float* xa = in + (size_t)rowA * INT_;
    const float* xb = in + (size_t)rowB * INT_;
    float4 a0 = *(const float4*)(xa + lane * 4);
    float4 a1 = *(const float4*)(xa + 128 + lane * 4);
    float4 b0 = *(const float4*)(xb + lane * 4);
    float4 b1 = *(const float4*)(xb + 128 + lane * 4);
    float sumA = a0.x + a0.y + a0.z + a0.w + a1.x + a1.y + a1.z + a1.w;
    float sqA  = a0.x * a0.x + a0.y * a0.y + a0.z * a0.z + a0.w * a0.w
               + a1.x * a1.x + a1.y * a1.y + a1.z * a1.z + a1.w * a1.w;
    float sumB = b0.x + b0.y + b0.z + b0.w + b1.x + b1.y + b1.z + b1.w;
    float sqB  = b0.x * b0.x + b0.y * b0.y + b0.z * b0.z + b0.w * b0.w
               + b1.x * b1.x + b1.y * b1.y + b1.z * b1.z + b1.w * b1.w;
#pragma unroll
    for (int o = 16; o > 0; o >>= 1) {
        sumA += __shfl_xor_sync(0xffffffffu, sumA, o);
        sqA  += __shfl_xor_sync(0xffffffffu, sqA,  o);
        sumB += __shfl_xor_sync(0xffffffffu, sumB, o);
        sqB  += __shfl_xor_sync(0xffffffffu, sqB,  o);
    }
    float meanA = sumA * (1.f / 256.f);
    float rstdA = rsqrtf(sqA * (1.f / 256.f) - meanA * meanA + 1e-5f);
    float meanB = sumB * (1.f / 256.f);
    float rstdB = rsqrtf(sqB * (1.f / 256.f) - meanB * meanB + 1e-5f);
    bf16* ya = out + (size_t)rowA * INT_;
    bf16* yb = out + (size_t)rowB * INT_;
#pragma unroll
    for (int half = 0; half < 2; half++) {
        int col = half * 128 + lane * 4;
        float4 s4 = *(const float4*)(s + col);
        float4 bb4 = *(const float4*)(b + col);
        float4 va = half ? a1 : a0;
        float4 vb = half ? b1 : b0;
        uint2 ua = make_uint2(
            packbf((va.x - meanA) * rstdA * s4.x + bb4.x,
                   (va.y - meanA) * rstdA * s4.y + bb4.y),
            packbf((va.z - meanA) * rstdA * s4.z + bb4.z,
                   (va.w - meanA) * rstdA * s4.w + bb4.w));
        uint2 ub = make_uint2(
            packbf((vb.x - meanB) * rstdB * s4.x + bb4.x,
                   (vb.y - meanB) * rstdB * s4.y + bb4.y),
            packbf((vb.z - meanB) * rstdB * s4.z + bb4.z,
                   (vb.w - meanB) * rstdB * s4.w + bb4.w));
        *(uint2*)(ya + col) = ua;
        *(uint2*)(yb + col) = ub;
    }
}

// ==================== Flash attention, 128-query tiles, split-KV (4 chunks) ====
// grid (N/128, B*H, 4), block 256 (8 warps). Dynamic smem 55296 B.
#define KT_PER_CHUNK 8
#define QT_ 128
#define ATT_QOFF 0u
#define ATT_KOFF (QT_ * 72 * 2)              // 18432
#define ATT_VOFF (ATT_KOFF + 2 * 64 * 72 * 2) // 36864
#define ATT_SMEM (ATT_VOFF + 2 * 64 * 72 * 2) // 55296

__global__ __launch_bounds__(256) void attn_part(const bf16* __restrict__ qk,
                                                 const __half* __restrict__ vh,
                                                 __half* __restrict__ Opart,
                                                 float* __restrict__ ml)
{
    extern __shared__ char asm_[];
    bf16*   Qs = (bf16*)(asm_ + ATT_QOFF);     // [128][72]
    const uint32_t smb = smem_u32(asm_);
    const uint32_t qs_base = smb + ATT_QOFF;
    const uint32_t ks_base = smb + ATT_KOFF;   // [2][64][72] bf16
    const uint32_t vs_base = smb + ATT_VOFF;   // [2][64][72] half

    const int tid  = threadIdx.x;
    const int lane = tid & 31;
    const int w    = tid >> 5;        // 0..7
    const int g  = lane >> 2;
    const int tg = lane & 3;
    const int bh = blockIdx.y;
    const int b = bh >> 2, h = bh & 3;
    const int q0 = blockIdx.x * QT_;
    const int ck = blockIdx.z;

    const int q8 = lane >> 3;
    const uint32_t k_lo = (uint32_t)(((((q8 >> 1) << 3) + (lane & 7)) * 72 + ((q8 & 1) << 3)) * 2);

    auto issueKV = [&](int kt) {
        const int p = kt & 1;
        const size_t krow = (size_t)(b * N_ + ck * (KT_PER_CHUNK * 64) + kt * 64);
        const bf16*  kb = qk + krow * 512 + 256 + h * 64;
        const __half* vb = vh + krow * 256 + h * 64;
#pragma unroll
        for (int i = 0; i < 2; i++) {
            int v = tid + i * 256;
            int r = v >> 3, s = v & 7;
            cp16(ks_base + (uint32_t)((p * 64 + r) * 72 + s * 8) * 2, kb + (size_t)r * 512 + s * 8);
            cp16(vs_base + (uint32_t)((p * 64 + r) * 72 + s * 8) * 2, vb + (size_t)r * 256 + s * 8);
        }
        CP_COMMIT();
    };

    issueKV(0);

    // load Q tile (sync loads): 128 rows x 64 bf16
    {
        const bf16* qb = qk + (size_t)(b * N_ + q0) * 512 + h * 64;
#pragma unroll
        for (int i = 0; i < 4; i++) {
            int v = tid + i * 256;
            int r = v >> 3, s = v & 7;
            *(uint4*)&Qs[r * 72 + s * 8] = *(const uint4*)(qb + (size_t)r * 512 + s * 8);
        }
    }
    __syncthreads();

    uint32_t qf[4][4];
    {
        const int r0 = w * 16 + g;
#pragma unroll
        for (int kc = 0; kc < 4; kc++) {
            qf[kc][0] = *(const uint32_t*)&Qs[(r0    ) * 72 + kc * 16 + tg * 2];
            qf[kc][1] = *(const uint32_t*)&Qs[(r0 + 8) * 72 + kc * 16 + tg * 2];
            qf[kc][2] = *(const uint32_t*)&Qs[(r0    ) * 72 + kc * 16 + 8 + tg * 2];
            qf[kc][3] = *(const uint32_t*)&Qs[(r0 + 8) * 72 + kc * 16 + 8 + tg * 2];
        }
    }

    const int q4 = lane >> 3;
    const int v_rowpart = (lane & 7) + 8 * (q4 & 1);
    const int v_colpart = 8 * (q4 >> 1);
    const uint32_t ONES2 = 0x3C003C00u;   // f16x2 {1,1}

    float m0 = -INFINITY, m1 = -INFINITY;
    float o[8][4], lacc[4];
#pragma unroll
    for (int nh = 0; nh < 8; nh++)
#pragma unroll
        for (int r = 0; r < 4; r++) o[nh][r] = 0.f;
#pragma unroll
    for (int r = 0; r < 4; r++) lacc[r] = 0.f;

    for (int kt = 0; kt < KT_PER_CHUNK; kt++) {
        const int p = kt & 1;
        if (kt + 1 < KT_PER_CHUNK) { issueKV(kt + 1); CP_WAIT(1); }
        else                       { CP_WAIT(0); }
        __syncthreads();

        // ---- S = Q K^T (log2 domain), K fragments via ldmatrix.x4 ----
        float s[8][4];
#pragma unroll
        for (int na = 0; na < 8; na++)
#pragma unroll
            for (int r = 0; r < 4; r++) s[na][r] = 0.f;
        const uint32_t kBase = ks_base + (uint32_t)(p * 64 * 144) + k_lo;
#pragma unroll
        for (int kc = 0; kc < 4; kc++) {
#pragma unroll
            for (int pr = 0; pr < 4; pr++) {
                uint32_t kb4[4];
                LDSM4(kb4[0], kb4[1], kb4[2], kb4[3],
                      kBase + (uint32_t)(pr * 16 * 144) + kc * 32);
                mma16816(s[2 * pr],     qf[kc], kb4[0], kb4[1]);
                mma16816(s[2 * pr + 1], qf[kc], kb4[2], kb4[3]);
            }
        }

        // ---- online softmax: max ----
        float mt0 = -INFINITY, mt1 = -INFINITY;
#pragma unroll
        for (int na = 0; na < 8; na++) {
            mt0 = fmaxf(mt0, fmaxf(s[na][0], s[na][1]));
            mt1 = fmaxf(mt1, fmaxf(s[na][2], s[na][3]));
        }
#pragma unroll
        for (int x = 1; x <= 2; x <<= 1) {
            mt0 = fmaxf(mt0, __shfl_xor_sync(0xffffffffu, mt0, x));
            mt1 = fmaxf(mt1, __shfl_xor_sync(0xffffffffu, mt1, x));
        }
        float mn0 = fmaxf(m0, mt0), mn1 = fmaxf(m1, mt1);
        float al0 = exp2f(m0 - mn0), al1 = exp2f(m1 - mn1);
        m0 = mn0; m1 = mn1;

        // ---- P = exp2(S - m) via f16x2 MUFU; directly the A-fragment ----
        uint32_t pf[4][4];
#pragma unroll
        for (int kc = 0; kc < 4; kc++) {
            pf[kc][0] = ex2_h2(s[2 * kc][0] - mn0,     s[2 * kc][1] - mn0);
            pf[kc][1] = ex2_h2(s[2 * kc][2] - mn1,     s[2 * kc][3] - mn1);
            pf[kc][2] = ex2_h2(s[2 * kc + 1][0] - mn0, s[2 * kc + 1][1] - mn0);
            pf[kc][3] = ex2_h2(s[2 * kc + 1][2] - mn1, s[2 * kc + 1][3] - mn1);
        }

        // ---- rescale O and l ----
#pragma unroll
        for (int nh = 0; nh < 8; nh++) {
            o[nh][0] *= al0; o[nh][1] *= al0;
            o[nh][2] *= al1; o[nh][3] *= al1;
        }
        lacc[0] *= al0; lacc[1] *= al0;
        lacc[2] *= al1; lacc[3] *= al1;

        // ---- O += P V ; l += P 1 ----
        const uint32_t vpb = vs_base + (uint32_t)(p * 64 * 72) * 2;
#pragma unroll
        for (int kc = 0; kc < 4; kc++) {
            mma16816h(lacc, pf[kc], ONES2, ONES2);
#pragma unroll
            for (int nh = 0; nh < 8; nh += 2) {
                uint32_t addr = vpb +
                    (uint32_t)((16 * kc + v_rowpart) * 144 + (nh * 8 + v_colpart) * 2);
                uint32_t b0, b1, b2, b3;
                asm volatile(
                    "ldmatrix.sync.aligned.m8n8.x4.trans.shared.b16 {%0,%1,%2,%3}, [%4];"
                    : "=r"(b0), "=r"(b1), "=r"(b2), "=r"(b3) : "r"(addr));
                mma16816h(o[nh],     pf[kc], b0, b1);
                mma16816h(o[nh + 1], pf[kc], b2, b3);
            }
        }
        __syncthreads();
    }

    // ---- write partial O (unnormalized, fp16) + m,l ----
    const int r0l = w * 16 + g;
    __half* Obase = Opart + ((size_t)(ck * 8 + bh) * N_ + q0) * 64;
#pragma unroll
    for (int nh = 0; nh < 8; nh++) {
        const int col = nh * 8 + tg * 2;
        *(uint32_t*)(Obase + (size_t)r0l * 64 + col)       = packh(o[nh][0], o[nh][1]);
        *(uint32_t*)(Obase + (size_t)(r0l + 8) * 64 + col) = packh(o[nh][2], o[nh][3]);
    }
    if (tg == 0) {
        size_t mi0 = ((size_t)(ck * 8 + bh) * N_ + q0 + r0l) * 2;
        size_t mi1 = ((size_t)(ck * 8 + bh) * N_ + q0 + r0l + 8) * 2;
        ml[mi0] = m0; ml[mi0 + 1] = lacc[0];
        ml[mi1] = m1; ml[mi1 + 1] = lacc[2];
    }
}

// ==================== attention combine (4 chunks, fp16 partials) ==========
__global__ __launch_bounds__(256) void attn_combine(const __half* __restrict__ Opart,
                                                    const float* __restrict__ ml,
                                                    bf16* __restrict__ out)
{
    int gw   = blockIdx.x * 8 + (threadIdx.x >> 5);   // 0..16383
    int lane = threadIdx.x & 31;
    int bh  = gw >> 11;
    int row = gw & 2047;
    int b = bh >> 2, h = bh & 3;

    float m[4], l[4];
#pragma unroll
    for (int c = 0; c < 4; c++) {
        size_t idx = ((size_t)(c * 8 + bh) * N_ + row) * 2;
        m[c] = ml[idx]; l[c] = ml[idx + 1];
    }
    float ms = fmaxf(fmaxf(m[0], m[1]), fmaxf(m[2], m[3]));
    float wsum = 0.f, a0 = 0.f, a1 = 0.f;
#pragma unroll
    for (int c = 0; c < 4; c++) {
        float wc = exp2f(m[c] - ms);
        wsum += wc * l[c];
        __half2 hv = *(const __half2*)(Opart + ((size_t)(c * 8 + bh) * N_ + row) * 64 + lane * 2);
        float2 v = __half22float2(hv);
        a0 += wc * v.x; a1 += wc * v.y;
    }
    float inv = 1.f / wsum;
    *(uint32_t*)(out + ((size_t)(b * N_ + row)) * INT_ + h * 64 + lane * 2) =
        packbf(a0 * inv, a1 * inv);
}

// ==================== host ====================
extern "C" void kernel_launch(void* const* d_in, const int* in_sizes, int n_in,
                              void* d_out, int out_size)
{
    (void)in_sizes; (void)n_in; (void)out_size;
    const float* x   = (const float*)d_in[0];
    const float* dw  = (const float*)d_in[1];
    const float* db  = (const float*)d_in[2];
    const float* nds = (const float*)d_in[3];
    const float* ndb = (const float*)d_in[4];
    const float* qw  = (const float*)d_in[5];
    const float* pw  = (const float*)d_in[6];
    const float* pb  = (const float*)d_in[7];
    const float* nms = (const float*)d_in[8];
    const float* nmb = (const float*)d_in[9];
    const float* m1w = (const float*)d_in[10];
    const float* m1b = (const float*)d_in[11];
    const float* m2w = (const float*)d_in[12];
    const float* m2b = (const float*)d_in[13];
    const float* uw  = (const float*)d_in[14];
    const float* ub  = (const float*)d_in[15];
    const float* gm  = (const float*)d_in[16];

    float *X, *Hb, *mlp, *cst, *lnt;
    __half *Opart;
    bf16 *qkbf, *xbf, *hnbf, *attbf, *g1bf, *hbf;
    __half* vh;
    bf16 *wd, *wq, *wp, *w1, *w2, *wu;
    cudaGetSymbolAddress((void**)&X,     g_X);
    cudaGetSymbolAddress((void**)&Hb,    g_H);
    cudaGetSymbolAddress((void**)&Opart, g_Opart);
    cudaGetSymbolAddress((void**)&mlp,   g_ml);
    cudaGetSymbolAddress((void**)&cst,   g_cs);
    cudaGetSymbolAddress((void**)&lnt,   g_lns);
    cudaGetSymbolAddress((void**)&qkbf,  g_qkbf);
    cudaGetSymbolAddress((void**)&vh,    g_vh);
    cudaGetSymbolAddress((void**)&xbf,   g_xbf);
    cudaGetSymbolAddress((void**)&hnbf,  g_hnbf);
    cudaGetSymbolAddress((void**)&attbf, g_attbf);
    cudaGetSymbolAddress((void**)&g1bf,  g_g1bf);
    cudaGetSymbolAddress((void**)&hbf,   g_hbf);
    cudaGetSymbolAddress((void**)&wd,    g_wdown);
    cudaGetSymbolAddress((void**)&wq,    g_wqkv);
    cudaGetSymbolAddress((void**)&wp,    g_wproj);
    cudaGetSymbolAddress((void**)&w1,    g_wm1);
    cudaGetSymbolAddress((void**)&w2,    g_wm2);
    cudaGetSymbolAddress((void**)&wu,    g_wup);

    const int SM3 = 3 * (BM_ + BN_) * 72 * 2;   // 55296
    cudaFuncSetAttribute(gemm_cp<0>, cudaFuncAttributeMaxDynamicSharedMemorySize, SM3);
    cudaFuncSetAttribute(gemm_cp<1>, cudaFuncAttributeMaxDynamicSharedMemorySize, SM3);
    cudaFuncSetAttribute(gemm_cp<2>, cudaFuncAttributeMaxDynamicSharedMemorySize, SM3);
    cudaFuncSetAttribute(gemm_cp<3>, cudaFuncAttributeMaxDynamicSharedMemorySize, SM3);
    cudaFuncSetAttribute(gemm_cp<5>, cudaFuncAttributeMaxDynamicSharedMemorySize, SM3);
    cudaFuncSetAttribute(attn_part,  cudaFuncAttributeMaxDynamicSharedMemorySize, ATT_SMEM);

    // rope tables (deterministic; every call)
    rope_init<<<(N_ * 32) / 256, 256>>>();

    // one batched convert for input x + all weights
    {
        ConvArgs a;
        const float* srcs[7] = {x, dw, qw, pw, m1w, m2w, uw};
        bf16* dsts[7] = {xbf, wd, wq, wp, w1, w2, wu};
        unsigned sizes[7] = {
            M_ * D_ / 4,
            (unsigned)(L_ * INT_ * D_ / 4),
            (unsigned)(L_ * 3 * INT_ * INT_ / 4),
            (unsigned)(L_ * INT_ * INT_ / 4),
            (unsigned)(L_ * HID_ * INT_ / 4),
            (unsigned)(L_ * INT_ * HID_ / 4),
            (unsigned)(L_ * D_ * INT_ / 4)};
        unsigned acc = 0;
        for (int i = 0; i < 7; i++) {
            a.src[i] = srcs[i]; a.dst[i] = dsts[i];
            acc += sizes[i]; a.end[i] = acc;
        }
        conv_all<<<(acc + 255) / 256, 256>>>(a, acc);
    }

    for (int l = 0; l < L_; l++) {
        const float* xin = (l == 0) ? x : X;
        float* xout = (l == L_ - 1) ? (float*)d_out : X;
        bf16* xbf_out = (l == L_ - 1) ? nullptr : xbf;

        // h = x @ down_w^T + down_b   [4096x256, K=1024] -> 256 CTAs
        gemm_cp<0><<<dim3(INT_ / 64, M_ / 64), GTHREADS, SM3>>>(
            xbf, wd + (size_t)l * INT_ * D_, db + (size_t)l * INT_,
            nullptr, nullptr, Hb, nullptr, nullptr, D_, INT_);
        // hn = LN(h) -> bf16
        ln_kernel<<<(M_ * 16) / 256, 256>>>(Hb, nds + (size_t)l * INT_,
                                            ndb + (size_t)l * INT_, hnbf);
        // qkv = hn @ qkv_w^T  with fused rope epilogue (tables) -> 768 CTAs
        gemm_cp<5><<<dim3(12, M_ / 64), GTHREADS, SM3>>>(
            hnbf, wq + (size_t)l * 3 * INT_ * INT_, nullptr,
            cst, lnt, nullptr, qkbf, vh, INT_, 768);
        // attention: 128-query tiles, 4 KV chunks -> 512 CTAs x 256 thr
        attn_part<<<dim3(N_ / QT_, B_ * H_, 4), 256, ATT_SMEM>>>(qkbf, vh, Opart, mlp);
        attn_combine<<<(8 * N_) / 8, 256>>>(Opart, mlp, attbf);
        // h = res + (o @ proj_w^T + proj_b)   -> 256 CTAs
        gemm_cp<2><<<dim3(INT_ / 64, M_ / 64), GTHREADS, SM3>>>(
            attbf, wp + (size_t)l * INT_ * INT_, pb + (size_t)l * INT_,
            Hb, nullptr, Hb, nullptr, nullptr, INT_, INT_);
        // m = LN(h) -> bf16
        ln_kernel<<<(M_ * 16) / 256, 256>>>(Hb, nms + (size_t)l * INT_,
                                            nmb + (size_t)l * INT_, hnbf);
        // g1 = gelu(m @ m1^T + b1) -> bf16 only   -> 512 CTAs
        gemm_cp<1><<<dim3(HID_ / 64, M_ / 64), GTHREADS, SM3>>>(
            hnbf, w1 + (size_t)l * HID_ * INT_, m1b + (size_t)l * HID_,
            nullptr, nullptr, nullptr, g1bf, nullptr, INT_, HID_);
        // h = h + (g1 @ m2^T + b2) -> fp32 Hb + bf16 hbf   -> 256 CTAs
        gemm_cp<2><<<dim3(INT_ / 64, M_ / 64), GTHREADS, SM3>>>(
            g1bf, w2 + (size_t)l * INT_ * HID_, m2b + (size_t)l * INT_,
            Hb, nullptr, Hb, hbf, nullptr, HID_, INT_);
        // x = shortcut + gamma * (h @ up^T + ub)   -> 1024 CTAs
        gemm_cp<3><<<dim3(D_ / 64, M_ / 64), GTHREADS, SM3>>>(
            hbf, wu + (size_t)l * D_ * INT_, ub + (size_t)l * D_,
            xin, gm + (size_t)l * D_, xout, xbf_out, nullptr, INT_, D_);
    }
}